// round 1
// baseline (speedup 1.0000x reference)
#include <cuda_runtime.h>
#include <cuda_bf16.h>

#define NB   8
#define CIN  256
#define COUT 4
#define ZD   32
#define VOX  (ZD*ZD*ZD)     // 32768
#define VOX4 (VOX/4)        // 8192
#define UD   64

// Scratch for the conv+residual result y: (B, COUT, 32,32,32) = 4 MB
__device__ float g_ybuf[NB * COUT * VOX];

// ---------------------------------------------------------------------------
// Kernel 1: y[b,o,v] = sum_i weight[o,i]*(S[b,i]+1)*x[b,i,v] + prev[b,o,v]
// One float4 of voxels per thread, 256-channel loop, coeffs in smem.
// ---------------------------------------------------------------------------
__global__ void __launch_bounds__(64) conv_mod_kernel(
    const float* __restrict__ x, const float* __restrict__ S,
    const float* __restrict__ prev, const float* __restrict__ weight)
{
    __shared__ float4 cw[CIN];
    const int tid = threadIdx.x;
    const int b = blockIdx.y;

    #pragma unroll
    for (int i = tid; i < CIN; i += 64) {
        float s = S[b * CIN + i] + 1.0f;
        float4 c;
        c.x = weight[0 * CIN + i] * s;
        c.y = weight[1 * CIN + i] * s;
        c.z = weight[2 * CIN + i] * s;
        c.w = weight[3 * CIN + i] * s;
        cw[i] = c;
    }
    __syncthreads();

    const int v = blockIdx.x * 64 + tid;   // float4 group within the 32^3 image
    const float4* xb = reinterpret_cast<const float4*>(x) + (size_t)b * CIN * VOX4 + v;

    float4 a0 = make_float4(0.f, 0.f, 0.f, 0.f);
    float4 a1 = a0, a2 = a0, a3 = a0;

    #pragma unroll 8
    for (int i = 0; i < CIN; i++) {
        float4 xv = xb[(size_t)i * VOX4];
        float4 c  = cw[i];
        a0.x = fmaf(c.x, xv.x, a0.x); a0.y = fmaf(c.x, xv.y, a0.y);
        a0.z = fmaf(c.x, xv.z, a0.z); a0.w = fmaf(c.x, xv.w, a0.w);
        a1.x = fmaf(c.y, xv.x, a1.x); a1.y = fmaf(c.y, xv.y, a1.y);
        a1.z = fmaf(c.y, xv.z, a1.z); a1.w = fmaf(c.y, xv.w, a1.w);
        a2.x = fmaf(c.z, xv.x, a2.x); a2.y = fmaf(c.z, xv.y, a2.y);
        a2.z = fmaf(c.z, xv.z, a2.z); a2.w = fmaf(c.z, xv.w, a2.w);
        a3.x = fmaf(c.w, xv.x, a3.x); a3.y = fmaf(c.w, xv.y, a3.y);
        a3.z = fmaf(c.w, xv.z, a3.z); a3.w = fmaf(c.w, xv.w, a3.w);
    }

    const float4* pb = reinterpret_cast<const float4*>(prev) + (size_t)b * COUT * VOX4 + v;
    float4* yb = reinterpret_cast<float4*>(g_ybuf) + (size_t)b * COUT * VOX4 + v;

    float4 p;
    p = pb[0 * VOX4]; a0.x += p.x; a0.y += p.y; a0.z += p.z; a0.w += p.w; yb[0 * VOX4] = a0;
    p = pb[1 * VOX4]; a1.x += p.x; a1.y += p.y; a1.z += p.z; a1.w += p.w; yb[1 * VOX4] = a1;
    p = pb[2 * VOX4]; a2.x += p.x; a2.y += p.y; a2.z += p.z; a2.w += p.w; yb[2 * VOX4] = a2;
    p = pb[3 * VOX4]; a3.x += p.x; a3.y += p.y; a3.z += p.z; a3.w += p.w; yb[3 * VOX4] = a3;
}

// ---------------------------------------------------------------------------
// Kernel 2: fused trilinear x2 upsample (half-pixel) + depthwise 3x3x3 blur
// (replicate pad). Collapsed into a per-axis 3-tap stencil directly on the
// 32^3 y grid. Each thread computes a 2x2x2 output block.
//
// For output coord u (0..63): blur taps hit upsample positions u-1,u,u+1
// (clamped); each upsample position v has 2 input taps:
//   v even: (m2-1, m2) w (0.25, 0.75);  v odd: (m2, m2+1) w (0.75, 0.25)
// with input indices clamped to [0,31] (exactly reproduces jax's edge
// renormalization). Combined weights land on y[m-1..m+1], m = u>>1.
// ---------------------------------------------------------------------------
__global__ void __launch_bounds__(256) upblur_kernel(float* __restrict__ out)
{
    __shared__ float wt[UD][3];
    const int tid = threadIdx.x;

    if (tid < UD) {
        const int u = tid;
        const int m = u >> 1;
        float w0 = 0.f, w1 = 0.f, w2 = 0.f;
        #pragma unroll
        for (int d = 0; d < 3; d++) {
            const float kb = (d == 1) ? (1.7f / 3.7f) : (1.0f / 3.7f);
            int vv = u + d - 1;
            vv = vv < 0 ? 0 : (vv > UD - 1 ? UD - 1 : vv);
            const int m2 = vv >> 1;
            const int p  = vv & 1;
            int j0 = p ? m2     : m2 - 1;
            int j1 = p ? m2 + 1 : m2;
            const float a0 = p ? 0.75f : 0.25f;
            const float a1 = p ? 0.25f : 0.75f;
            j0 = j0 < 0 ? 0 : j0;
            j1 = j1 > ZD - 1 ? ZD - 1 : j1;
            const int o0 = j0 - m + 1;
            const int o1 = j1 - m + 1;
            if      (o0 == 0) w0 += kb * a0;
            else if (o0 == 1) w1 += kb * a0;
            else              w2 += kb * a0;
            if      (o1 == 0) w0 += kb * a1;
            else if (o1 == 1) w1 += kb * a1;
            else              w2 += kb * a1;
        }
        wt[u][0] = w0; wt[u][1] = w1; wt[u][2] = w2;
    }
    __syncthreads();

    const int idx = blockIdx.x * 256 + tid;
    const int my = idx & 31;
    const int mx = (idx >> 5) & 31;
    const int mz = (idx >> 10) & 31;
    const int bc = idx >> 15;                 // b*COUT + c, 0..31
    const float* __restrict__ yb = g_ybuf + (size_t)bc * VOX;

    int zi[3], xi[3], yi[3];
    zi[0] = mz > 0 ? mz - 1 : 0; zi[1] = mz; zi[2] = mz < ZD - 1 ? mz + 1 : ZD - 1;
    xi[0] = mx > 0 ? mx - 1 : 0; xi[1] = mx; xi[2] = mx < ZD - 1 ? mx + 1 : ZD - 1;
    yi[0] = my > 0 ? my - 1 : 0; yi[1] = my; yi[2] = my < ZD - 1 ? my + 1 : ZD - 1;

    float v[3][3][3];
    #pragma unroll
    for (int i = 0; i < 3; i++) {
        #pragma unroll
        for (int j = 0; j < 3; j++) {
            const float* row = yb + (zi[i] * ZD + xi[j]) * ZD;
            v[i][j][0] = row[yi[0]];
            v[i][j][1] = row[yi[1]];
            v[i][j][2] = row[yi[2]];
        }
    }

    const float* wy0 = wt[2 * my];
    const float* wy1 = wt[2 * my + 1];
    float sy[3][3][2];
    #pragma unroll
    for (int i = 0; i < 3; i++) {
        #pragma unroll
        for (int j = 0; j < 3; j++) {
            sy[i][j][0] = v[i][j][0] * wy0[0] + v[i][j][1] * wy0[1] + v[i][j][2] * wy0[2];
            sy[i][j][1] = v[i][j][0] * wy1[0] + v[i][j][1] * wy1[1] + v[i][j][2] * wy1[2];
        }
    }

    const float* wx0 = wt[2 * mx];
    const float* wx1 = wt[2 * mx + 1];
    float sx[3][2][2];
    #pragma unroll
    for (int i = 0; i < 3; i++) {
        #pragma unroll
        for (int py = 0; py < 2; py++) {
            sx[i][0][py] = sy[i][0][py] * wx0[0] + sy[i][1][py] * wx0[1] + sy[i][2][py] * wx0[2];
            sx[i][1][py] = sy[i][0][py] * wx1[0] + sy[i][1][py] * wx1[1] + sy[i][2][py] * wx1[2];
        }
    }

    const float* wz0 = wt[2 * mz];
    const float* wz1 = wt[2 * mz + 1];
    float r[2][2][2];
    #pragma unroll
    for (int px = 0; px < 2; px++) {
        #pragma unroll
        for (int py = 0; py < 2; py++) {
            r[0][px][py] = sx[0][px][py] * wz0[0] + sx[1][px][py] * wz0[1] + sx[2][px][py] * wz0[2];
            r[1][px][py] = sx[0][px][py] * wz1[0] + sx[1][px][py] * wz1[1] + sx[2][px][py] * wz1[2];
        }
    }

    float* ob = out + (size_t)bc * (UD * UD * UD);
    #pragma unroll
    for (int pz = 0; pz < 2; pz++) {
        #pragma unroll
        for (int px = 0; px < 2; px++) {
            size_t off = ((size_t)(2 * mz + pz) * UD + (2 * mx + px)) * UD + 2 * my;
            float2 val = make_float2(r[pz][px][0], r[pz][px][1]);
            *reinterpret_cast<float2*>(ob + off) = val;
        }
    }
}

// ---------------------------------------------------------------------------
extern "C" void kernel_launch(void* const* d_in, const int* in_sizes, int n_in,
                              void* d_out, int out_size)
{
    const float* x      = (const float*)d_in[0];   // (8,256,32,32,32)
    const float* S      = (const float*)d_in[1];   // (8,256)
    const float* prev   = (const float*)d_in[2];   // (8,4,32,32,32)
    const float* weight = (const float*)d_in[3];   // (4,256)
    float* out = (float*)d_out;                    // (8,4,64,64,64)

    conv_mod_kernel<<<dim3(VOX4 / 64, NB), 64>>>(x, S, prev, weight);
    upblur_kernel<<<(NB * COUT * VOX) / 256, 256>>>(out);
}

// round 2
// speedup vs baseline: 1.1924x; 1.1924x over previous
#include <cuda_runtime.h>
#include <cuda_bf16.h>

#define NB   8
#define CIN  256
#define COUT 4
#define ZD   32
#define VOX  (ZD*ZD*ZD)     // 32768
#define VOX4 (VOX/4)        // 8192
#define UD   64

// Scratch for the conv+residual result y: (B, COUT, 32,32,32) = 4 MB
__device__ float g_ybuf[NB * COUT * VOX];

// ---------------------------------------------------------------------------
// Kernel 1: y[b,o,v] = sum_i weight[o,i]*(S[b,i]+1)*x[b,i,v] + prev[b,o,v]
// 256 threads/block: 4 channel-chunks x 64 voxel-float4s, smem reduction.
// ---------------------------------------------------------------------------
__global__ void __launch_bounds__(256) conv_mod_kernel(
    const float* __restrict__ x, const float* __restrict__ S,
    const float* __restrict__ prev, const float* __restrict__ weight)
{
    __shared__ float4 cw[CIN];                 // 4 KB
    __shared__ float4 part[4][64][COUT];       // 16 KB [chunk][vl][outch]
    const int tid = threadIdx.x;
    const int b = blockIdx.y;

    {
        const int i = tid;                     // 256 threads, one coeff each
        const float s = S[b * CIN + i] + 1.0f;
        cw[i] = make_float4(weight[0 * CIN + i] * s,
                            weight[1 * CIN + i] * s,
                            weight[2 * CIN + i] * s,
                            weight[3 * CIN + i] * s);
    }
    __syncthreads();

    const int chunk = tid >> 6;                // 0..3 -> channels [64*chunk, 64*chunk+64)
    const int vl    = tid & 63;
    const int v     = blockIdx.x * 64 + vl;    // float4 group within 32^3 image
    const float4* xb = reinterpret_cast<const float4*>(x)
                     + (size_t)b * CIN * VOX4 + (size_t)(chunk * 64) * VOX4 + v;
    const float4* cc = cw + chunk * 64;

    float4 a0 = make_float4(0.f, 0.f, 0.f, 0.f);
    float4 a1 = a0, a2 = a0, a3 = a0;

    #pragma unroll 8
    for (int i = 0; i < 64; i++) {
        float4 xv = xb[(size_t)i * VOX4];
        float4 c  = cc[i];
        a0.x = fmaf(c.x, xv.x, a0.x); a0.y = fmaf(c.x, xv.y, a0.y);
        a0.z = fmaf(c.x, xv.z, a0.z); a0.w = fmaf(c.x, xv.w, a0.w);
        a1.x = fmaf(c.y, xv.x, a1.x); a1.y = fmaf(c.y, xv.y, a1.y);
        a1.z = fmaf(c.y, xv.z, a1.z); a1.w = fmaf(c.y, xv.w, a1.w);
        a2.x = fmaf(c.z, xv.x, a2.x); a2.y = fmaf(c.z, xv.y, a2.y);
        a2.z = fmaf(c.z, xv.z, a2.z); a2.w = fmaf(c.z, xv.w, a2.w);
        a3.x = fmaf(c.w, xv.x, a3.x); a3.y = fmaf(c.w, xv.y, a3.y);
        a3.z = fmaf(c.w, xv.z, a3.z); a3.w = fmaf(c.w, xv.w, a3.w);
    }

    part[chunk][vl][0] = a0;
    part[chunk][vl][1] = a1;
    part[chunk][vl][2] = a2;
    part[chunk][vl][3] = a3;
    __syncthreads();

    // Thread (chunk, vl) reduces output channel oc=chunk at voxel vl.
    const int oc = chunk;
    float4 r0 = part[0][vl][oc];
    float4 r1 = part[1][vl][oc];
    float4 r2 = part[2][vl][oc];
    float4 r3 = part[3][vl][oc];
    float4 r;
    r.x = (r0.x + r1.x) + (r2.x + r3.x);
    r.y = (r0.y + r1.y) + (r2.y + r3.y);
    r.z = (r0.z + r1.z) + (r2.z + r3.z);
    r.w = (r0.w + r1.w) + (r2.w + r3.w);

    const size_t oidx = (size_t)b * COUT * VOX4 + (size_t)oc * VOX4 + v;
    float4 p = reinterpret_cast<const float4*>(prev)[oidx];
    r.x += p.x; r.y += p.y; r.z += p.z; r.w += p.w;
    reinterpret_cast<float4*>(g_ybuf)[oidx] = r;
}

// ---------------------------------------------------------------------------
// Kernel 2: fused trilinear x2 upsample (half-pixel) + depthwise 3x3x3 blur
// (replicate pad), collapsed to a per-axis 3-tap stencil on the 32^3 grid.
// Block covers a (2 z x 4 x x 32 y) cell tile; halo loaded to smem.
// Each thread produces a 2x2x2 output block from its 3x3x3 smem neighborhood.
// ---------------------------------------------------------------------------
__global__ void __launch_bounds__(256) upblur_kernel(float* __restrict__ out)
{
    __shared__ float wt[UD][3];
    __shared__ float sm[4][6][34];             // [dz][dx][dy] halo tile, 3.3 KB

    const int tid = threadIdx.x;

    // Per-output-coordinate combined 3-tap weights (same for z/x/y axes).
    if (tid < UD) {
        const int u = tid;
        const int m = u >> 1;
        float w0 = 0.f, w1 = 0.f, w2 = 0.f;
        #pragma unroll
        for (int d = 0; d < 3; d++) {
            const float kb = (d == 1) ? (1.7f / 3.7f) : (1.0f / 3.7f);
            int vv = u + d - 1;
            vv = vv < 0 ? 0 : (vv > UD - 1 ? UD - 1 : vv);
            const int m2 = vv >> 1;
            const int p  = vv & 1;
            int j0 = p ? m2     : m2 - 1;
            int j1 = p ? m2 + 1 : m2;
            const float a0 = p ? 0.75f : 0.25f;
            const float a1 = p ? 0.25f : 0.75f;
            j0 = j0 < 0 ? 0 : j0;
            j1 = j1 > ZD - 1 ? ZD - 1 : j1;
            const int o0 = j0 - m + 1;
            const int o1 = j1 - m + 1;
            if      (o0 == 0) w0 += kb * a0;
            else if (o0 == 1) w1 += kb * a0;
            else              w2 += kb * a0;
            if      (o1 == 0) w0 += kb * a1;
            else if (o1 == 1) w1 += kb * a1;
            else              w2 += kb * a1;
        }
        wt[u][0] = w0; wt[u][1] = w1; wt[u][2] = w2;
    }

    const int mxT = blockIdx.x;                // 0..7  -> mx0 = 4*mxT
    const int mzT = blockIdx.y;                // 0..15 -> mz0 = 2*mzT
    const int bc  = blockIdx.z;                // 0..31 (b*COUT + c)
    const int mx0 = mxT * 4;
    const int mz0 = mzT * 2;
    const float* __restrict__ yb = g_ybuf + (size_t)bc * VOX;

    // Cooperative halo load with replicate clamping: z in [mz0-1, mz0+2],
    // x in [mx0-1, mx0+4], y in [-1, 32].
    for (int e = tid; e < 4 * 6 * 34; e += 256) {
        const int dz = e / (6 * 34);
        const int rr = e - dz * (6 * 34);
        const int dx = rr / 34;
        const int dy = rr - dx * 34;
        int gz = mz0 - 1 + dz; gz = gz < 0 ? 0 : (gz > ZD - 1 ? ZD - 1 : gz);
        int gx = mx0 - 1 + dx; gx = gx < 0 ? 0 : (gx > ZD - 1 ? ZD - 1 : gx);
        int gy = dy - 1;       gy = gy < 0 ? 0 : (gy > ZD - 1 ? ZD - 1 : gy);
        sm[dz][dx][dy] = yb[(gz * ZD + gx) * ZD + gy];
    }
    __syncthreads();

    const int ly = tid & 31;
    const int lx = (tid >> 5) & 3;
    const int lz = tid >> 7;                   // 0..1
    const int my = ly;
    const int mx = mx0 + lx;
    const int mz = mz0 + lz;

    float v[3][3][3];
    #pragma unroll
    for (int i = 0; i < 3; i++)
        #pragma unroll
        for (int j = 0; j < 3; j++) {
            v[i][j][0] = sm[lz + i][lx + j][ly + 0];
            v[i][j][1] = sm[lz + i][lx + j][ly + 1];
            v[i][j][2] = sm[lz + i][lx + j][ly + 2];
        }

    const float* wy0 = wt[2 * my];
    const float* wy1 = wt[2 * my + 1];
    float sy[3][3][2];
    #pragma unroll
    for (int i = 0; i < 3; i++)
        #pragma unroll
        for (int j = 0; j < 3; j++) {
            sy[i][j][0] = v[i][j][0] * wy0[0] + v[i][j][1] * wy0[1] + v[i][j][2] * wy0[2];
            sy[i][j][1] = v[i][j][0] * wy1[0] + v[i][j][1] * wy1[1] + v[i][j][2] * wy1[2];
        }

    const float* wx0 = wt[2 * mx];
    const float* wx1 = wt[2 * mx + 1];
    float sx[3][2][2];
    #pragma unroll
    for (int i = 0; i < 3; i++)
        #pragma unroll
        for (int py = 0; py < 2; py++) {
            sx[i][0][py] = sy[i][0][py] * wx0[0] + sy[i][1][py] * wx0[1] + sy[i][2][py] * wx0[2];
            sx[i][1][py] = sy[i][0][py] * wx1[0] + sy[i][1][py] * wx1[1] + sy[i][2][py] * wx1[2];
        }

    const float* wz0 = wt[2 * mz];
    const float* wz1 = wt[2 * mz + 1];
    float r[2][2][2];
    #pragma unroll
    for (int px = 0; px < 2; px++)
        #pragma unroll
        for (int py = 0; py < 2; py++) {
            r[0][px][py] = sx[0][px][py] * wz0[0] + sx[1][px][py] * wz0[1] + sx[2][px][py] * wz0[2];
            r[1][px][py] = sx[0][px][py] * wz1[0] + sx[1][px][py] * wz1[1] + sx[2][px][py] * wz1[2];
        }

    float* ob = out + (size_t)bc * (UD * UD * UD);
    #pragma unroll
    for (int pz = 0; pz < 2; pz++)
        #pragma unroll
        for (int px = 0; px < 2; px++) {
            size_t off = ((size_t)(2 * mz + pz) * UD + (2 * mx + px)) * UD + 2 * my;
            *reinterpret_cast<float2*>(ob + off) = make_float2(r[pz][px][0], r[pz][px][1]);
        }
}

// ---------------------------------------------------------------------------
extern "C" void kernel_launch(void* const* d_in, const int* in_sizes, int n_in,
                              void* d_out, int out_size)
{
    const float* x      = (const float*)d_in[0];   // (8,256,32,32,32)
    const float* S      = (const float*)d_in[1];   // (8,256)
    const float* prev   = (const float*)d_in[2];   // (8,4,32,32,32)
    const float* weight = (const float*)d_in[3];   // (4,256)
    float* out = (float*)d_out;                    // (8,4,64,64,64)

    conv_mod_kernel<<<dim3(VOX4 / 64, NB), 256>>>(x, S, prev, weight);
    upblur_kernel<<<dim3(8, 16, NB * COUT), 256>>>(out);
}

// round 3
// speedup vs baseline: 1.3261x; 1.1122x over previous
#include <cuda_runtime.h>
#include <cuda_bf16.h>

#define NB   8
#define CIN  256
#define COUT 4
#define ZD   32
#define VOX  (ZD*ZD*ZD)     // 32768
#define VOX4 (VOX/4)        // 8192
#define UD   64

// Scratch for the conv+residual result y: (B, COUT, 32,32,32) = 4 MB
__device__ float g_ybuf[NB * COUT * VOX];

// ---------------------------------------------------------------------------
// Kernel 1: y[b,o,v] = sum_i weight[o,i]*(S[b,i]+1)*x[b,i,v] + prev[b,o,v]
// 128 threads/block: 4 channel-chunks x 32 voxel-float4s, padded smem reduce.
// 2048 blocks -> fine-grained load balance across 148 SMs.
// ---------------------------------------------------------------------------
__global__ void __launch_bounds__(128) conv_mod_kernel(
    const float* __restrict__ x, const float* __restrict__ S,
    const float* __restrict__ prev, const float* __restrict__ weight)
{
    __shared__ float4 cw[CIN];        // 4 KB
    __shared__ float4 part[32][17];   // [vl][chunk*4+oc], padded: 8.7 KB
    const int tid = threadIdx.x;
    const int b = blockIdx.y;

    #pragma unroll
    for (int i = tid; i < CIN; i += 128) {
        const float s = S[b * CIN + i] + 1.0f;
        cw[i] = make_float4(weight[0 * CIN + i] * s,
                            weight[1 * CIN + i] * s,
                            weight[2 * CIN + i] * s,
                            weight[3 * CIN + i] * s);
    }
    __syncthreads();

    const int chunk = tid >> 5;                // 0..3 -> channels [64*chunk, ..+64)
    const int vl    = tid & 31;
    const int v     = blockIdx.x * 32 + vl;    // float4 group within 32^3 image
    const float4* xb = reinterpret_cast<const float4*>(x)
                     + (size_t)b * CIN * VOX4 + (size_t)(chunk * 64) * VOX4 + v;
    const float4* cc = cw + chunk * 64;

    float4 a0 = make_float4(0.f, 0.f, 0.f, 0.f);
    float4 a1 = a0, a2 = a0, a3 = a0;

    #pragma unroll 8
    for (int i = 0; i < 64; i++) {
        float4 xv = __ldcs(&xb[(size_t)i * VOX4]);
        float4 c  = cc[i];
        a0.x = fmaf(c.x, xv.x, a0.x); a0.y = fmaf(c.x, xv.y, a0.y);
        a0.z = fmaf(c.x, xv.z, a0.z); a0.w = fmaf(c.x, xv.w, a0.w);
        a1.x = fmaf(c.y, xv.x, a1.x); a1.y = fmaf(c.y, xv.y, a1.y);
        a1.z = fmaf(c.y, xv.z, a1.z); a1.w = fmaf(c.y, xv.w, a1.w);
        a2.x = fmaf(c.z, xv.x, a2.x); a2.y = fmaf(c.z, xv.y, a2.y);
        a2.z = fmaf(c.z, xv.z, a2.z); a2.w = fmaf(c.z, xv.w, a2.w);
        a3.x = fmaf(c.w, xv.x, a3.x); a3.y = fmaf(c.w, xv.y, a3.y);
        a3.z = fmaf(c.w, xv.z, a3.z); a3.w = fmaf(c.w, xv.w, a3.w);
    }

    part[vl][chunk * 4 + 0] = a0;
    part[vl][chunk * 4 + 1] = a1;
    part[vl][chunk * 4 + 2] = a2;
    part[vl][chunk * 4 + 3] = a3;
    __syncthreads();

    // Thread (oc=chunk, vl) reduces output channel oc at voxel vl.
    const int oc = chunk;
    float4 r0 = part[vl][0 * 4 + oc];
    float4 r1 = part[vl][1 * 4 + oc];
    float4 r2 = part[vl][2 * 4 + oc];
    float4 r3 = part[vl][3 * 4 + oc];
    float4 r;
    r.x = (r0.x + r1.x) + (r2.x + r3.x);
    r.y = (r0.y + r1.y) + (r2.y + r3.y);
    r.z = (r0.z + r1.z) + (r2.z + r3.z);
    r.w = (r0.w + r1.w) + (r2.w + r3.w);

    const size_t oidx = (size_t)b * COUT * VOX4 + (size_t)oc * VOX4 + v;
    float4 p = __ldcs(&reinterpret_cast<const float4*>(prev)[oidx]);
    r.x += p.x; r.y += p.y; r.z += p.z; r.w += p.w;
    reinterpret_cast<float4*>(g_ybuf)[oidx] = r;
}

// ---------------------------------------------------------------------------
// Kernel 2: fused trilinear x2 upsample + depthwise 3x3x3 blur, collapsed to
// a 3-tap stencil with CONSTANT per-parity weights on replicate-clamped halo:
//   even output: (1.175, 2.275, 0.25)/3.7 ; odd output: mirrored.
// (Identity holds at borders because clamped-tap weights fold onto the
//  replicated halo values exactly.)
// Block tile: 4z x 4x x 32y cells; thread tile: 1z x 1x x 2y cells
// (= 2x2x4 outputs). All weights are FFMA immediates.
// ---------------------------------------------------------------------------
#define WE0 0.31756757f   // 1.175/3.7
#define WE1 0.61486486f   // 2.275/3.7
#define WE2 0.06756757f   // 0.25/3.7

__global__ void __launch_bounds__(256) upblur_kernel(float* __restrict__ out)
{
    __shared__ float sm[6][6][35];             // [dz][dx][dy], pad 35: 5 KB

    const int tid = threadIdx.x;
    const int mx0 = blockIdx.x * 4;
    const int mz0 = blockIdx.y * 4;
    const int bc  = blockIdx.z;                // b*COUT + c, 0..31
    const float* __restrict__ yb = g_ybuf + (size_t)bc * VOX;

    // Cooperative replicate-clamped halo: z,x in [t0-1, t0+4], y in [-1, 32].
    for (int e = tid; e < 6 * 6 * 34; e += 256) {
        const int dz = e / (6 * 34);
        const int rr = e - dz * (6 * 34);
        const int dx = rr / 34;
        const int dy = rr - dx * 34;
        int gz = mz0 - 1 + dz; gz = gz < 0 ? 0 : (gz > ZD - 1 ? ZD - 1 : gz);
        int gx = mx0 - 1 + dx; gx = gx < 0 ? 0 : (gx > ZD - 1 ? ZD - 1 : gx);
        int gy = dy - 1;       gy = gy < 0 ? 0 : (gy > ZD - 1 ? ZD - 1 : gy);
        sm[dz][dx][dy] = yb[(gz * ZD + gx) * ZD + gy];
    }
    __syncthreads();

    const int ly2 = tid & 15;                  // y cell-pair: cells 2*ly2, 2*ly2+1
    const int lx  = (tid >> 4) & 3;
    const int lz  = tid >> 6;                  // 0..3
    const int y0  = 2 * ly2;                   // input y window [y0-1, y0+2]

    // Load 3x3x4 neighborhood.
    float v[3][3][4];
    #pragma unroll
    for (int i = 0; i < 3; i++)
        #pragma unroll
        for (int j = 0; j < 3; j++)
            #pragma unroll
            for (int k = 0; k < 4; k++)
                v[i][j][k] = sm[lz + i][lx + j][y0 + k];

    // y-pass: 4 outputs per (i,j): cell0 even/odd, cell1 even/odd.
    float sy[3][3][4];
    #pragma unroll
    for (int i = 0; i < 3; i++)
        #pragma unroll
        for (int j = 0; j < 3; j++) {
            sy[i][j][0] = fmaf(WE0, v[i][j][0], fmaf(WE1, v[i][j][1], WE2 * v[i][j][2]));
            sy[i][j][1] = fmaf(WE2, v[i][j][0], fmaf(WE1, v[i][j][1], WE0 * v[i][j][2]));
            sy[i][j][2] = fmaf(WE0, v[i][j][1], fmaf(WE1, v[i][j][2], WE2 * v[i][j][3]));
            sy[i][j][3] = fmaf(WE2, v[i][j][1], fmaf(WE1, v[i][j][2], WE0 * v[i][j][3]));
        }

    // x-pass: even/odd sub-x.
    float sx[3][2][4];
    #pragma unroll
    for (int i = 0; i < 3; i++)
        #pragma unroll
        for (int k = 0; k < 4; k++) {
            sx[i][0][k] = fmaf(WE0, sy[i][0][k], fmaf(WE1, sy[i][1][k], WE2 * sy[i][2][k]));
            sx[i][1][k] = fmaf(WE2, sy[i][0][k], fmaf(WE1, sy[i][1][k], WE0 * sy[i][2][k]));
        }

    // z-pass.
    float r[2][2][4];
    #pragma unroll
    for (int px = 0; px < 2; px++)
        #pragma unroll
        for (int k = 0; k < 4; k++) {
            r[0][px][k] = fmaf(WE0, sx[0][px][k], fmaf(WE1, sx[1][px][k], WE2 * sx[2][px][k]));
            r[1][px][k] = fmaf(WE2, sx[0][px][k], fmaf(WE1, sx[1][px][k], WE0 * sx[2][px][k]));
        }

    const int mz = mz0 + lz;
    const int mx = mx0 + lx;
    float* ob = out + (size_t)bc * (UD * UD * UD);
    #pragma unroll
    for (int pz = 0; pz < 2; pz++)
        #pragma unroll
        for (int px = 0; px < 2; px++) {
            const size_t off = ((size_t)(2 * mz + pz) * UD + (2 * mx + px)) * UD + 4 * ly2;
            float4 val = make_float4(r[pz][px][0], r[pz][px][1], r[pz][px][2], r[pz][px][3]);
            __stcs(reinterpret_cast<float4*>(ob + off), val);
        }
}

// ---------------------------------------------------------------------------
extern "C" void kernel_launch(void* const* d_in, const int* in_sizes, int n_in,
                              void* d_out, int out_size)
{
    const float* x      = (const float*)d_in[0];   // (8,256,32,32,32)
    const float* S      = (const float*)d_in[1];   // (8,256)
    const float* prev   = (const float*)d_in[2];   // (8,4,32,32,32)
    const float* weight = (const float*)d_in[3];   // (4,256)
    float* out = (float*)d_out;                    // (8,4,64,64,64)

    conv_mod_kernel<<<dim3(VOX4 / 32, NB), 128>>>(x, S, prev, weight);
    upblur_kernel<<<dim3(8, 8, NB * COUT), 256>>>(out);
}

// round 4
// speedup vs baseline: 1.4030x; 1.0580x over previous
#include <cuda_runtime.h>
#include <cuda_bf16.h>

#define NB   8
#define CIN  256
#define COUT 4
#define ZD   32
#define VOX  (ZD*ZD*ZD)     // 32768
#define VOX4 (VOX/4)        // 8192
#define UD   64

#define CONV_BLOCKS 2048            // 256 per batch, batch-major
#define CONV_PER_BATCH 256
#define UP_BLOCKS   (NB*COUT*128)   // 4096: 128 tiles (2z x 4x x 32y cells) per bc

// Collapsed upsample+blur 3-tap weights (constant everywhere incl. borders
// thanks to replicate-clamped halo): even output (WE0,WE1,WE2), odd mirrored.
#define WE0 0.31756757f   // 1.175/3.7
#define WE1 0.61486486f   // 2.275/3.7
#define WE2 0.06756757f   // 0.25/3.7

__device__ float g_ybuf[NB * COUT * VOX];   // conv+residual result (4 MB)
__device__ int   g_done[NB];                // per-batch conv completion counters

__global__ void reset_kernel() {
    if (threadIdx.x < NB) g_done[threadIdx.x] = 0;
}

__global__ void __launch_bounds__(128) fused_kernel(
    const float* __restrict__ x, const float* __restrict__ S,
    const float* __restrict__ prev, const float* __restrict__ weight,
    float* __restrict__ out)
{
    const int bid = blockIdx.x;
    const int tid = threadIdx.x;

    if (bid < CONV_BLOCKS) {
        // ============== Phase 1: modulated 1x1x1 conv + residual ==============
        __shared__ float4 cw[CIN];        // 4 KB coeffs
        __shared__ float4 part[32][17];   // padded partials, 8.7 KB

        const int b    = bid >> 8;        // batch-major!
        const int vblk = bid & 255;

        #pragma unroll
        for (int i = tid; i < CIN; i += 128) {
            const float s = S[b * CIN + i] + 1.0f;
            cw[i] = make_float4(weight[0 * CIN + i] * s,
                                weight[1 * CIN + i] * s,
                                weight[2 * CIN + i] * s,
                                weight[3 * CIN + i] * s);
        }
        __syncthreads();

        const int chunk = tid >> 5;              // 0..3 -> 64 channels each
        const int vl    = tid & 31;
        const int v     = vblk * 32 + vl;
        const float4* xb = reinterpret_cast<const float4*>(x)
                         + (size_t)b * CIN * VOX4 + (size_t)(chunk * 64) * VOX4 + v;
        const float4* cc = cw + chunk * 64;

        float4 a0 = make_float4(0.f, 0.f, 0.f, 0.f);
        float4 a1 = a0, a2 = a0, a3 = a0;

        for (int i0 = 0; i0 < 64; i0 += 8) {
            float4 xv[8];
            #pragma unroll
            for (int j = 0; j < 8; j++)
                xv[j] = __ldcs(&xb[(size_t)(i0 + j) * VOX4]);
            #pragma unroll
            for (int j = 0; j < 8; j++) {
                const float4 c = cc[i0 + j];
                a0.x = fmaf(c.x, xv[j].x, a0.x); a0.y = fmaf(c.x, xv[j].y, a0.y);
                a0.z = fmaf(c.x, xv[j].z, a0.z); a0.w = fmaf(c.x, xv[j].w, a0.w);
                a1.x = fmaf(c.y, xv[j].x, a1.x); a1.y = fmaf(c.y, xv[j].y, a1.y);
                a1.z = fmaf(c.y, xv[j].z, a1.z); a1.w = fmaf(c.y, xv[j].w, a1.w);
                a2.x = fmaf(c.z, xv[j].x, a2.x); a2.y = fmaf(c.z, xv[j].y, a2.y);
                a2.z = fmaf(c.z, xv[j].z, a2.z); a2.w = fmaf(c.z, xv[j].w, a2.w);
                a3.x = fmaf(c.w, xv[j].x, a3.x); a3.y = fmaf(c.w, xv[j].y, a3.y);
                a3.z = fmaf(c.w, xv[j].z, a3.z); a3.w = fmaf(c.w, xv[j].w, a3.w);
            }
        }

        part[vl][chunk * 4 + 0] = a0;
        part[vl][chunk * 4 + 1] = a1;
        part[vl][chunk * 4 + 2] = a2;
        part[vl][chunk * 4 + 3] = a3;
        __syncthreads();

        const int oc = chunk;
        float4 r0 = part[vl][0 * 4 + oc];
        float4 r1 = part[vl][1 * 4 + oc];
        float4 r2 = part[vl][2 * 4 + oc];
        float4 r3 = part[vl][3 * 4 + oc];
        float4 r;
        r.x = (r0.x + r1.x) + (r2.x + r3.x);
        r.y = (r0.y + r1.y) + (r2.y + r3.y);
        r.z = (r0.z + r1.z) + (r2.z + r3.z);
        r.w = (r0.w + r1.w) + (r2.w + r3.w);

        const size_t oidx = (size_t)b * COUT * VOX4 + (size_t)oc * VOX4 + v;
        float4 p = __ldcs(&reinterpret_cast<const float4*>(prev)[oidx]);
        r.x += p.x; r.y += p.y; r.z += p.z; r.w += p.w;
        reinterpret_cast<float4*>(g_ybuf)[oidx] = r;   // plain store: stays L2-hot

        __threadfence();          // release y stores
        __syncthreads();
        if (tid == 0) atomicAdd(&g_done[b], 1);

    } else {
        // ============== Phase 2: fused upsample x2 + blur ==============
        __shared__ float sm[4][6][35];     // [dz][dx][dy] halo, padded, 3.4 KB

        const int ub = bid - CONV_BLOCKS;
        const int bc = ub >> 7;            // 0..31 (b*COUT + c)
        const int t  = ub & 127;           // tile within bc
        const int zT = t >> 3;             // 0..15
        const int xT = t & 7;              // 0..7
        const int b  = bc >> 2;
        const int mz0 = zT * 2;
        const int mx0 = xT * 4;

        // Wait for this batch's conv to complete.
        if (tid == 0) {
            while (*(volatile int*)&g_done[b] < CONV_PER_BATCH) { /* spin */ }
        }
        __syncthreads();
        __threadfence();          // acquire y stores

        const float* __restrict__ yb = g_ybuf + (size_t)bc * VOX;

        // Replicate-clamped halo: z in [mz0-1, mz0+2], x in [mx0-1, mx0+4],
        // y in [-1, 32].  4*6*34 = 816 elements.
        for (int e = tid; e < 4 * 6 * 34; e += 128) {
            const int dz = e / (6 * 34);
            const int rr = e - dz * (6 * 34);
            const int dx = rr / 34;
            const int dy = rr - dx * 34;
            int gz = mz0 - 1 + dz; gz = gz < 0 ? 0 : (gz > ZD - 1 ? ZD - 1 : gz);
            int gx = mx0 - 1 + dx; gx = gx < 0 ? 0 : (gx > ZD - 1 ? ZD - 1 : gx);
            int gy = dy - 1;       gy = gy < 0 ? 0 : (gy > ZD - 1 ? ZD - 1 : gy);
            sm[dz][dx][dy] = yb[(gz * ZD + gx) * ZD + gy];
        }
        __syncthreads();

        const int ly2 = tid & 15;          // y cell-pair index
        const int lx  = (tid >> 4) & 3;
        const int lz  = tid >> 6;          // 0..1
        const int y0  = 2 * ly2;

        float v[3][3][4];
        #pragma unroll
        for (int i = 0; i < 3; i++)
            #pragma unroll
            for (int j = 0; j < 3; j++)
                #pragma unroll
                for (int k = 0; k < 4; k++)
                    v[i][j][k] = sm[lz + i][lx + j][y0 + k];

        float sy[3][3][4];
        #pragma unroll
        for (int i = 0; i < 3; i++)
            #pragma unroll
            for (int j = 0; j < 3; j++) {
                sy[i][j][0] = fmaf(WE0, v[i][j][0], fmaf(WE1, v[i][j][1], WE2 * v[i][j][2]));
                sy[i][j][1] = fmaf(WE2, v[i][j][0], fmaf(WE1, v[i][j][1], WE0 * v[i][j][2]));
                sy[i][j][2] = fmaf(WE0, v[i][j][1], fmaf(WE1, v[i][j][2], WE2 * v[i][j][3]));
                sy[i][j][3] = fmaf(WE2, v[i][j][1], fmaf(WE1, v[i][j][2], WE0 * v[i][j][3]));
            }

        float sx[3][2][4];
        #pragma unroll
        for (int i = 0; i < 3; i++)
            #pragma unroll
            for (int k = 0; k < 4; k++) {
                sx[i][0][k] = fmaf(WE0, sy[i][0][k], fmaf(WE1, sy[i][1][k], WE2 * sy[i][2][k]));
                sx[i][1][k] = fmaf(WE2, sy[i][0][k], fmaf(WE1, sy[i][1][k], WE0 * sy[i][2][k]));
            }

        float r[2][2][4];
        #pragma unroll
        for (int px = 0; px < 2; px++)
            #pragma unroll
            for (int k = 0; k < 4; k++) {
                r[0][px][k] = fmaf(WE0, sx[0][px][k], fmaf(WE1, sx[1][px][k], WE2 * sx[2][px][k]));
                r[1][px][k] = fmaf(WE2, sx[0][px][k], fmaf(WE1, sx[1][px][k], WE0 * sx[2][px][k]));
            }

        const int mz = mz0 + lz;
        const int mx = mx0 + lx;
        float* ob = out + (size_t)bc * (UD * UD * UD);
        #pragma unroll
        for (int pz = 0; pz < 2; pz++)
            #pragma unroll
            for (int px = 0; px < 2; px++) {
                const size_t off = ((size_t)(2 * mz + pz) * UD + (2 * mx + px)) * UD + 4 * ly2;
                *reinterpret_cast<float4*>(ob + off) =
                    make_float4(r[pz][px][0], r[pz][px][1], r[pz][px][2], r[pz][px][3]);
            }
    }
}

// ---------------------------------------------------------------------------
extern "C" void kernel_launch(void* const* d_in, const int* in_sizes, int n_in,
                              void* d_out, int out_size)
{
    const float* x      = (const float*)d_in[0];   // (8,256,32,32,32)
    const float* S      = (const float*)d_in[1];   // (8,256)
    const float* prev   = (const float*)d_in[2];   // (8,4,32,32,32)
    const float* weight = (const float*)d_in[3];   // (4,256)
    float* out = (float*)d_out;                    // (8,4,64,64,64)

    reset_kernel<<<1, 32>>>();
    fused_kernel<<<CONV_BLOCKS + UP_BLOCKS, 128>>>(x, S, prev, weight, out);
}